// round 1
// baseline (speedup 1.0000x reference)
#include <cuda_runtime.h>
#include <math.h>

#define N_TOT 512
#define D_DIM 512

// Scratch (no allocations allowed in kernel_launch)
__device__ float  g_E[N_TOT * N_TOT];    // exp(-dist/t), diagonal forced to 0
__device__ float  g_LO[N_TOT * N_TOT];   // -dist/t
__device__ float  g_norm[N_TOT];
__device__ double g_acc;

__device__ __forceinline__ const float* frow(const float* wt, const float* mt, int r) {
    return (r < 256) ? (wt + r * D_DIM) : (mt + (r - 256) * D_DIM);
}

// Kernel 1: row squared-norms (one warp per row) + zero the accumulator
__global__ void norms_kernel(const float* __restrict__ wt, const float* __restrict__ mt) {
    if (blockIdx.x == 0 && threadIdx.x == 0) g_acc = 0.0;
    int warps_per_block = blockDim.x / 32;
    int row = blockIdx.x * warps_per_block + (threadIdx.x >> 5);
    int lane = threadIdx.x & 31;
    if (row >= N_TOT) return;
    const float* f = frow(wt, mt, row);
    float s = 0.f;
    #pragma unroll
    for (int d = lane; d < D_DIM; d += 32) {
        float v = f[d];
        s = fmaf(v, v, s);
    }
    #pragma unroll
    for (int o = 16; o; o >>= 1) s += __shfl_xor_sync(0xffffffffu, s, o);
    if (lane == 0) g_norm[row] = s;
}

// Kernel 2: tiled fp32 GEMM G = F F^T, epilogue computes lo = -dist/2 and e = exp(lo)
#define BM 64
#define BN 64
#define BK 16
__global__ void gemm_dist_kernel(const float* __restrict__ wt, const float* __restrict__ mt) {
    __shared__ float sA[BK][BM + 1];
    __shared__ float sB[BK][BN + 1];
    int t  = threadIdx.x;            // 256 threads
    int tx = t & 15;
    int ty = t >> 4;
    int i0 = blockIdx.y * BM;
    int j0 = blockIdx.x * BN;

    float acc[4][4] = {};

    int lk = t & 15;   // k index for loads
    int lm = t >> 4;   // row base (16 rows per pass)

    for (int k0 = 0; k0 < D_DIM; k0 += BK) {
        #pragma unroll
        for (int p = 0; p < 4; p++) {
            int m = lm + p * 16;
            sA[lk][m] = frow(wt, mt, i0 + m)[k0 + lk];
            sB[lk][m] = frow(wt, mt, j0 + m)[k0 + lk];
        }
        __syncthreads();
        #pragma unroll
        for (int kk = 0; kk < BK; kk++) {
            float a[4], b[4];
            #pragma unroll
            for (int u = 0; u < 4; u++) a[u] = sA[kk][ty * 4 + u];
            #pragma unroll
            for (int v = 0; v < 4; v++) b[v] = sB[kk][tx * 4 + v];
            #pragma unroll
            for (int u = 0; u < 4; u++)
                #pragma unroll
                for (int v = 0; v < 4; v++)
                    acc[u][v] = fmaf(a[u], b[v], acc[u][v]);
        }
        __syncthreads();
    }

    // Epilogue: sq = ni + nj - 2*g ; dist = sqrt(max(sq,0)) ; lo = -dist/2 ; e = exp(lo)
    #pragma unroll
    for (int u = 0; u < 4; u++) {
        int i = i0 + ty * 4 + u;
        float ni = g_norm[i];
        #pragma unroll
        for (int v = 0; v < 4; v++) {
            int j = j0 + tx * 4 + v;
            float sq = ni + g_norm[j] - 2.f * acc[u][v];
            float dist = sqrtf(fmaxf(sq, 0.f));
            float lo = -0.5f * dist;                 // temperature = 2.0
            float e = (i == j) ? 0.f : expf(lo);
            g_LO[i * N_TOT + j] = lo;
            g_E[i * N_TOT + j] = e;
        }
    }
}

// Kernel 3: per-row masked denom + term sum. Block = row i, thread = positive idx k.
__global__ void loss_kernel(const float* __restrict__ lw, const float* __restrict__ lm) {
    __shared__ float sE[N_TOT];
    __shared__ float sLD[N_TOT];
    __shared__ float red[16];

    int i = blockIdx.x;
    int k = threadIdx.x;   // 512 threads

    float yi = (i < 256) ? lw[i] : lm[i - 256];
    float yk = (k < 256) ? lw[k] : lm[k - 256];
    float ldk = fabsf(yi - yk);
    sLD[k] = ldk;
    sE[k]  = g_E[i * N_TOT + k];
    __syncthreads();

    // denom = sum_j e[i,j] * (ld[i,j] >= ld[i,k]); e[i,i]=0 so j=i contributes nothing
    const float4* ld4 = (const float4*)sLD;
    const float4* e4  = (const float4*)sE;
    float denom = 0.f;
    #pragma unroll 8
    for (int j = 0; j < N_TOT / 4; j++) {
        float4 l = ld4[j];
        float4 e = e4[j];
        denom += (l.x >= ldk) ? e.x : 0.f;
        denom += (l.y >= ldk) ? e.y : 0.f;
        denom += (l.z >= ldk) ? e.z : 0.f;
        denom += (l.w >= ldk) ? e.w : 0.f;
    }

    float term = (k == i) ? 0.f : (g_LO[i * N_TOT + k] - logf(denom));

    // block reduce
    #pragma unroll
    for (int o = 16; o; o >>= 1) term += __shfl_xor_sync(0xffffffffu, term, o);
    int w = k >> 5, lane = k & 31;
    if (lane == 0) red[w] = term;
    __syncthreads();
    if (w == 0) {
        float s = (lane < 16) ? red[lane] : 0.f;
        #pragma unroll
        for (int o = 8; o; o >>= 1) s += __shfl_xor_sync(0xffffffffu, s, o);
        if (lane == 0) atomicAdd(&g_acc, (double)s);
    }
}

__global__ void finalize_kernel(float* out) {
    out[0] = (float)(-g_acc / (double)(N_TOT * (N_TOT - 1)));
}

extern "C" void kernel_launch(void* const* d_in, const int* in_sizes, int n_in,
                              void* d_out, int out_size) {
    const float* wt = (const float*)d_in[0];
    const float* mt = (const float*)d_in[1];
    const float* lw = (const float*)d_in[2];
    const float* lm = (const float*)d_in[3];
    float* out = (float*)d_out;

    norms_kernel<<<64, 256>>>(wt, mt);                 // 8 warps/block * 64 = 512 rows
    gemm_dist_kernel<<<dim3(8, 8), 256>>>(wt, mt);
    loss_kernel<<<N_TOT, N_TOT>>>(lw, lm);
    finalize_kernel<<<1, 1>>>(out);
}

// round 2
// speedup vs baseline: 2.3013x; 2.3013x over previous
#include <cuda_runtime.h>
#include <math.h>

#define N_TOT 512
#define D_DIM 512

__device__ float  g_LO[N_TOT * N_TOT];   // lo = -dist/2, natural order
__device__ float  g_ys[N_TOT];           // labels sorted ascending
__device__ int    g_perm[N_TOT];         // g_ys[m] = y[g_perm[m]]
__device__ double g_acc;
__device__ int    g_count;

__device__ __forceinline__ const float* frow(const float* wt, const float* mt, int r) {
    return (r < 256) ? (wt + r * D_DIM) : (mt + (r - 256) * D_DIM);
}
__device__ __forceinline__ float lab(const float* lw, const float* lm, int r) {
    return (r < 256) ? lw[r] : lm[r - 256];
}

// ---------------------------------------------------------------------------
// Kernel 1: bitonic sort of the 512 labels (key + original index), and reset
// of the accumulator / completion counter (needed per graph replay).
// ---------------------------------------------------------------------------
__global__ void sort_kernel(const float* __restrict__ lw, const float* __restrict__ lm) {
    __shared__ float y[N_TOT];
    __shared__ int   idx[N_TOT];
    int k = threadIdx.x;
    if (k == 0) { g_acc = 0.0; g_count = 0; }
    y[k] = lab(lw, lm, k);
    idx[k] = k;
    __syncthreads();
    for (int size = 2; size <= N_TOT; size <<= 1) {
        for (int stride = size >> 1; stride > 0; stride >>= 1) {
            int j = k ^ stride;
            if (j > k) {
                bool up = ((k & size) == 0);
                float yk = y[k], yj = y[j];
                if ((yk > yj) == up) {
                    y[k] = yj; y[j] = yk;
                    int t = idx[k]; idx[k] = idx[j]; idx[j] = t;
                }
            }
            __syncthreads();
        }
    }
    g_ys[k] = y[k];
    g_perm[k] = idx[k];
}

// ---------------------------------------------------------------------------
// Kernel 2: Gram GEMM (F F^T) with in-block norm accumulation; epilogue writes
// lo = -0.5*sqrt(max(ni+nj-2g, 0)). Tiles 64(i) x 32(j), BK=32, 128 threads,
// grid (16, 8) = 128 blocks. Register-staged double buffering on the k-loop.
// ---------------------------------------------------------------------------
#define BM 64
#define BN 32
#define BK 32
#define NK_ITERS (D_DIM / BK)

__global__ void gemm_dist_kernel(const float* __restrict__ wt, const float* __restrict__ mt) {
    __shared__ float sA[2][BK][BM + 4];
    __shared__ float sB[2][BK][BN + 4];
    __shared__ float sNA[BM];
    __shared__ float sNB[BN];

    int t  = threadIdx.x;        // 128
    int tx = t & 7;              // j group (8 groups of 4)
    int ty = t >> 3;             // i group (16 groups of 4)
    int i0 = blockIdx.y * BM;
    int j0 = blockIdx.x * BN;

    float acc[4][4] = {};
    float na[4] = {}, nb[4] = {};

    // thread -> load mapping (A: 4 float4, B: 2 float4 per k-chunk)
    int arow[4], akq[4], brow[2], bkq[2];
    #pragma unroll
    for (int r = 0; r < 4; r++) { int fid = t + r * 128; arow[r] = fid >> 3; akq[r] = fid & 7; }
    #pragma unroll
    for (int r = 0; r < 2; r++) { int fid = t + r * 128; brow[r] = fid >> 3; bkq[r] = fid & 7; }

    // preload tile 0
    float4 pa[4], pb[2];
    #pragma unroll
    for (int r = 0; r < 4; r++)
        pa[r] = ((const float4*)(frow(wt, mt, i0 + arow[r])))[akq[r]];
    #pragma unroll
    for (int r = 0; r < 2; r++)
        pb[r] = ((const float4*)(frow(wt, mt, j0 + brow[r])))[bkq[r]];

    #pragma unroll
    for (int r = 0; r < 4; r++) {
        sA[0][akq[r]*4+0][arow[r]] = pa[r].x; sA[0][akq[r]*4+1][arow[r]] = pa[r].y;
        sA[0][akq[r]*4+2][arow[r]] = pa[r].z; sA[0][akq[r]*4+3][arow[r]] = pa[r].w;
    }
    #pragma unroll
    for (int r = 0; r < 2; r++) {
        sB[0][bkq[r]*4+0][brow[r]] = pb[r].x; sB[0][bkq[r]*4+1][brow[r]] = pb[r].y;
        sB[0][bkq[r]*4+2][brow[r]] = pb[r].z; sB[0][bkq[r]*4+3][brow[r]] = pb[r].w;
    }
    __syncthreads();

    for (int n = 0; n < NK_ITERS; n++) {
        int cur = n & 1;
        if (n + 1 < NK_ITERS) {
            int k0 = (n + 1) * BK;
            #pragma unroll
            for (int r = 0; r < 4; r++)
                pa[r] = ((const float4*)(frow(wt, mt, i0 + arow[r]) + k0))[akq[r]];
            #pragma unroll
            for (int r = 0; r < 2; r++)
                pb[r] = ((const float4*)(frow(wt, mt, j0 + brow[r]) + k0))[bkq[r]];
        }

        #pragma unroll 8
        for (int kk = 0; kk < BK; kk++) {
            float4 a4 = *(const float4*)&sA[cur][kk][ty * 4];
            float4 b4 = *(const float4*)&sB[cur][kk][tx * 4];
            float a[4] = {a4.x, a4.y, a4.z, a4.w};
            float b[4] = {b4.x, b4.y, b4.z, b4.w};
            if (tx == 0) {
                #pragma unroll
                for (int u = 0; u < 4; u++) na[u] = fmaf(a[u], a[u], na[u]);
            }
            if (ty == 0) {
                #pragma unroll
                for (int v = 0; v < 4; v++) nb[v] = fmaf(b[v], b[v], nb[v]);
            }
            #pragma unroll
            for (int u = 0; u < 4; u++)
                #pragma unroll
                for (int v = 0; v < 4; v++)
                    acc[u][v] = fmaf(a[u], b[v], acc[u][v]);
        }

        if (n + 1 < NK_ITERS) {
            int nxt = cur ^ 1;
            #pragma unroll
            for (int r = 0; r < 4; r++) {
                sA[nxt][akq[r]*4+0][arow[r]] = pa[r].x; sA[nxt][akq[r]*4+1][arow[r]] = pa[r].y;
                sA[nxt][akq[r]*4+2][arow[r]] = pa[r].z; sA[nxt][akq[r]*4+3][arow[r]] = pa[r].w;
            }
            #pragma unroll
            for (int r = 0; r < 2; r++) {
                sB[nxt][bkq[r]*4+0][brow[r]] = pb[r].x; sB[nxt][bkq[r]*4+1][brow[r]] = pb[r].y;
                sB[nxt][bkq[r]*4+2][brow[r]] = pb[r].z; sB[nxt][bkq[r]*4+3][brow[r]] = pb[r].w;
            }
            __syncthreads();
        }
    }

    if (tx == 0) {
        #pragma unroll
        for (int u = 0; u < 4; u++) sNA[ty * 4 + u] = na[u];
    }
    if (ty == 0) {
        #pragma unroll
        for (int v = 0; v < 4; v++) sNB[tx * 4 + v] = nb[v];
    }
    __syncthreads();

    #pragma unroll
    for (int u = 0; u < 4; u++) {
        int i = i0 + ty * 4 + u;
        float ni = sNA[ty * 4 + u];
        float4 o;
        float* op = &o.x;
        #pragma unroll
        for (int v = 0; v < 4; v++) {
            float sq = ni + sNB[tx * 4 + v] - 2.f * acc[u][v];
            op[v] = -0.5f * sqrtf(fmaxf(sq, 0.f));   // temperature 2.0
        }
        *(float4*)&g_LO[i * N_TOT + j0 + tx * 4] = o;
    }
}

// ---------------------------------------------------------------------------
// Kernel 3: per-row loss. Block = row i, thread = position/positive index k.
// denom via prefix sums over label-sorted e + two binary searches (exact
// predicate fabsf(yi - yj) >= t, monotone on each side of yi).
// ---------------------------------------------------------------------------
__global__ void loss_kernel(const float* __restrict__ lw, const float* __restrict__ lm,
                            float* __restrict__ out) {
    __shared__ float sLO[N_TOT];
    __shared__ float sY[N_TOT];
    __shared__ float sP[N_TOT + 1];
    __shared__ float warpS[16];

    int i = blockIdx.x;
    int k = threadIdx.x;    // 512
    int lane = k & 31, w = k >> 5;

    sLO[k] = g_LO[i * N_TOT + k];
    sY[k]  = g_ys[k];
    int pm = g_perm[k];
    float yi = lab(lw, lm, i);
    float yk = lab(lw, lm, k);
    __syncthreads();

    // e in sorted order, diagonal forced to 0
    float e = (pm == i) ? 0.f : expf(sLO[pm]);

    // exclusive prefix sum of e
    float v = e;
    #pragma unroll
    for (int o = 1; o < 32; o <<= 1) {
        float nvl = __shfl_up_sync(0xffffffffu, v, o);
        if (lane >= o) v += nvl;
    }
    if (lane == 31) warpS[w] = v;
    __syncthreads();
    if (w == 0) {
        float s = (lane < 16) ? warpS[lane] : 0.f;
        #pragma unroll
        for (int o = 1; o < 16; o <<= 1) {
            float nvl = __shfl_up_sync(0xffffffffu, s, o);
            if (lane >= o) s += nvl;
        }
        if (lane < 16) warpS[lane] = s;
    }
    __syncthreads();
    float off = (w > 0) ? warpS[w - 1] : 0.f;
    float S = warpS[15];
    sP[k] = off + v - e;
    if (k == N_TOT - 1) sP[N_TOT] = off + v;
    __syncthreads();

    // binary searches (exact same predicate as reference)
    float t = fabsf(yi - yk);
    int lo_ = 0, hi_ = N_TOT;
    while (lo_ < hi_) { int mid = (lo_ + hi_) >> 1; if (sY[mid] >= yi) hi_ = mid; else lo_ = mid + 1; }
    int p = lo_;
    lo_ = 0; hi_ = p;   // a = first m in [0,p) with fabsf(yi - sY[m]) < t
    while (lo_ < hi_) { int mid = (lo_ + hi_) >> 1; if (fabsf(yi - sY[mid]) < t) hi_ = mid; else lo_ = mid + 1; }
    int a = lo_;
    lo_ = p; hi_ = N_TOT;  // b = first m in [p,n) with fabsf(yi - sY[m]) >= t
    while (lo_ < hi_) { int mid = (lo_ + hi_) >> 1; if (fabsf(yi - sY[mid]) >= t) hi_ = mid; else lo_ = mid + 1; }
    int b = lo_;

    float denom = sP[a] + (S - sP[b]);
    float term = (k == i) ? 0.f : (sLO[k] - logf(denom));

    // block reduce (reuse warpS after a sync)
    #pragma unroll
    for (int o = 16; o; o >>= 1) term += __shfl_xor_sync(0xffffffffu, term, o);
    __syncthreads();
    if (lane == 0) warpS[w] = term;
    __syncthreads();
    if (k == 0) {
        float s = 0.f;
        #pragma unroll
        for (int q = 0; q < 16; q++) s += warpS[q];
        atomicAdd(&g_acc, (double)s);
        __threadfence();
        int done = atomicAdd(&g_count, 1);
        if (done == N_TOT - 1) {
            double total = atomicAdd(&g_acc, 0.0);  // all adds visible (fence+count)
            out[0] = (float)(-total / (double)(N_TOT * (N_TOT - 1)));
        }
    }
}

extern "C" void kernel_launch(void* const* d_in, const int* in_sizes, int n_in,
                              void* d_out, int out_size) {
    const float* wt = (const float*)d_in[0];
    const float* mt = (const float*)d_in[1];
    const float* lw = (const float*)d_in[2];
    const float* lm = (const float*)d_in[3];
    float* out = (float*)d_out;

    sort_kernel<<<1, N_TOT>>>(lw, lm);
    gemm_dist_kernel<<<dim3(16, 8), 128>>>(wt, mt);
    loss_kernel<<<N_TOT, N_TOT>>>(lw, lm, out);
}